// round 4
// baseline (speedup 1.0000x reference)
#include <cuda_runtime.h>
#include <cuda_bf16.h>
#include <math.h>

#define N_NODES  100000
#define N_EDGES  3200000
#define D_FEAT   128
#define HIDDEN   64
#define N_GRAPHS 64
#define N_CLASSES 10

// ---------------- scratch (device globals; no allocation allowed) -----------
__device__ __align__(16) float g_deg[N_NODES];
__device__ __align__(16) float g_dinv[N_NODES];
__device__ __align__(16) float g_h[N_NODES * HIDDEN];     // transformed features (X@W)
__device__ __align__(16) float g_hin[N_NODES * HIDDEN];   // relu'd layer output
__device__ __align__(16) float g_agg[N_NODES * HIDDEN];   // scatter accumulator
__device__ __align__(16) float g_gsum[N_GRAPHS * HIDDEN];
__device__ __align__(16) float g_gcnt[N_GRAPHS];

// ---------------- degree / norm ---------------------------------------------
__global__ void k_init_deg() {
    int i = blockIdx.x * blockDim.x + threadIdx.x;
    if (i < N_NODES) g_deg[i] = 1.0f;   // self-loop
}

__global__ void k_deg_edges(const int* __restrict__ dst) {
    int e = blockIdx.x * blockDim.x + threadIdx.x;
    if (e < N_EDGES) atomicAdd(&g_deg[dst[e]], 1.0f);
}

__global__ void k_dinv() {
    int i = blockIdx.x * blockDim.x + threadIdx.x;
    if (i < N_NODES) g_dinv[i] = rsqrtf(g_deg[i]);   // deg >= 1 always
}

// ---------------- dense GEMM: Y[N,64] = X[N,K] @ W[K,64] --------------------
// Block computes 32 rows x 64 cols. Thread tile: 4 rows x 2 cols (c, c+32).
template <int K>
__global__ void k_gemm(const float* __restrict__ X, const float* __restrict__ W,
                       float* __restrict__ Y) {
    __shared__ float Ws[K * 64];
    __shared__ float Xs[32 * K];
    const int t = threadIdx.x;
    const int row0 = blockIdx.x * 32;

    for (int i = t; i < K * 64; i += 256) Ws[i] = W[i];
    for (int i = t; i < 32 * K; i += 256) Xs[i] = X[(size_t)row0 * K + i];
    __syncthreads();

    const int c0 = t & 31;          // cols c0 and c0+32 (conflict-free Ws reads)
    const int r0 = (t >> 5) * 4;    // 4 consecutive local rows

    float acc[4][2] = {};
#pragma unroll 4
    for (int k = 0; k < K; k++) {
        float w0 = Ws[k * 64 + c0];
        float w1 = Ws[k * 64 + c0 + 32];
#pragma unroll
        for (int i = 0; i < 4; i++) {
            float xv = Xs[(r0 + i) * K + k];
            acc[i][0] += xv * w0;
            acc[i][1] += xv * w1;
        }
    }
#pragma unroll
    for (int i = 0; i < 4; i++) {
        size_t base = (size_t)(row0 + r0 + i) * 64;
        Y[base + c0]      = acc[i][0];
        Y[base + c0 + 32] = acc[i][1];
    }
}

// ---------------- self-loop init: agg = h * dinv^2 --------------------------
__global__ void k_self_init(const float* __restrict__ h) {
    int i = blockIdx.x * blockDim.x + threadIdx.x;   // over N*H/4 float4 chunks
    if (i >= N_NODES * HIDDEN / 4) return;
    int node = i / (HIDDEN / 4);
    float s = g_dinv[node]; s *= s;
    float4 v = reinterpret_cast<const float4*>(h)[i];
    v.x *= s; v.y *= s; v.z *= s; v.w *= s;
    reinterpret_cast<float4*>(g_agg)[i] = v;
}

// ---------------- edge scatter: agg[dst] += h[src] * dinv[s]*dinv[d] --------
// 16 threads per edge, one float4 gather each; 4 scalar atomicAdd (-> REDG).
__global__ void k_scatter(const int* __restrict__ src,
                          const int* __restrict__ dst,
                          const float* __restrict__ h) {
    long long tid = (long long)blockIdx.x * blockDim.x + threadIdx.x;
    int e = (int)(tid >> 4);
    if (e >= N_EDGES) return;
    int c = (int)(tid & 15);
    int s = src[e];
    int d = dst[e];
    float w = g_dinv[s] * g_dinv[d];
    float4 v = *reinterpret_cast<const float4*>(h + (size_t)s * 64 + c * 4);
    float* p = g_agg + (size_t)d * 64 + c * 4;
    atomicAdd(p + 0, v.x * w);
    atomicAdd(p + 1, v.y * w);
    atomicAdd(p + 2, v.z * w);
    atomicAdd(p + 3, v.w * w);
}

// ---------------- bias + relu: hin = relu(agg + b) ---------------------------
__global__ void k_bias_relu(const float* __restrict__ b) {
    int i = blockIdx.x * blockDim.x + threadIdx.x;   // over N*H/4 float4 chunks
    if (i >= N_NODES * HIDDEN / 4) return;
    int f4 = i & (HIDDEN / 4 - 1);
    float4 bb = reinterpret_cast<const float4*>(b)[f4];
    float4 v = reinterpret_cast<const float4*>(g_agg)[i];
    v.x = fmaxf(v.x + bb.x, 0.f);
    v.y = fmaxf(v.y + bb.y, 0.f);
    v.z = fmaxf(v.z + bb.z, 0.f);
    v.w = fmaxf(v.w + bb.w, 0.f);
    reinterpret_cast<float4*>(g_hin)[i] = v;
}

// ---------------- pooling ----------------------------------------------------
__global__ void k_pool_zero() {
    int i = blockIdx.x * blockDim.x + threadIdx.x;
    if (i < N_GRAPHS * HIDDEN) g_gsum[i] = 0.f;
    if (i < N_GRAPHS) g_gcnt[i] = 0.f;
}

// batch is sorted -> run-length accumulate per block, flush on graph change.
// Applies bias b2 + relu inline (layer-2 epilogue fused here).
__global__ void k_pool(const int* __restrict__ batch,
                       const float* __restrict__ b2) {
    const int f = threadIdx.x;  // 0..63
    const int chunk = (N_NODES + gridDim.x - 1) / gridDim.x;
    int n0 = blockIdx.x * chunk;
    if (n0 >= N_NODES) return;
    int n1 = min(n0 + chunk, N_NODES);

    const float bf = b2[f];
    int cur = batch[n0];
    float acc = 0.f, cnt = 0.f;
    for (int n = n0; n < n1; n++) {
        int bt = batch[n];
        if (bt != cur) {
            atomicAdd(&g_gsum[cur * HIDDEN + f], acc);
            if (f == 0) atomicAdd(&g_gcnt[cur], cnt);
            acc = 0.f; cnt = 0.f; cur = bt;
        }
        acc += fmaxf(g_agg[(size_t)n * HIDDEN + f] + bf, 0.f);
        cnt += 1.f;
    }
    atomicAdd(&g_gsum[cur * HIDDEN + f], acc);
    if (f == 0) atomicAdd(&g_gcnt[cur], cnt);
}

// ---------------- head: mean, linear, log_softmax ----------------------------
__global__ void k_head(const float* __restrict__ linW, const float* __restrict__ linb,
                       float* __restrict__ out) {
    int g = threadIdx.x;
    if (g >= N_GRAPHS) return;
    float inv = 1.0f / fmaxf(g_gcnt[g], 1.0f);
    float logits[N_CLASSES];
#pragma unroll
    for (int c = 0; c < N_CLASSES; c++) logits[c] = linb[c];
    for (int f = 0; f < HIDDEN; f++) {
        float p = g_gsum[g * HIDDEN + f] * inv;
#pragma unroll
        for (int c = 0; c < N_CLASSES; c++) logits[c] += p * linW[f * N_CLASSES + c];
    }
    float m = logits[0];
#pragma unroll
    for (int c = 1; c < N_CLASSES; c++) m = fmaxf(m, logits[c]);
    float s = 0.f;
#pragma unroll
    for (int c = 0; c < N_CLASSES; c++) s += expf(logits[c] - m);
    float l = logf(s) + m;
#pragma unroll
    for (int c = 0; c < N_CLASSES; c++) out[g * N_CLASSES + c] = logits[c] - l;
}

// ---------------- launch ------------------------------------------------------
extern "C" void kernel_launch(void* const* d_in, const int* in_sizes, int n_in,
                              void* d_out, int out_size) {
    const float* x     = (const float*)d_in[0];
    const int*   ei    = (const int*)d_in[1];     // JAX x64 disabled -> int32
    const int*   batch = (const int*)d_in[2];
    const float* W1    = (const float*)d_in[3];
    const float* b1    = (const float*)d_in[4];
    const float* W2    = (const float*)d_in[5];
    const float* b2    = (const float*)d_in[6];
    const float* linW  = (const float*)d_in[7];
    const float* linb  = (const float*)d_in[8];
    float* out = (float*)d_out;

    const int* src = ei;
    const int* dst = ei + N_EDGES;

    float *p_h, *p_hin;
    cudaGetSymbolAddress((void**)&p_h, g_h);
    cudaGetSymbolAddress((void**)&p_hin, g_hin);

    const int NT = 256;
    const int nodeBlocks = (N_NODES + NT - 1) / NT;
    const int edgeBlocks = (N_EDGES + NT - 1) / NT;
    const int featChunks = N_NODES * HIDDEN / 4;
    const int featBlocks = (featChunks + NT - 1) / NT;
    const long long scatterThreads = (long long)N_EDGES * 16;
    const int scatterBlocks = (int)((scatterThreads + NT - 1) / NT);

    // normalization
    k_init_deg<<<nodeBlocks, NT>>>();
    k_deg_edges<<<edgeBlocks, NT>>>(dst);
    k_dinv<<<nodeBlocks, NT>>>();

    // layer 1: h = x@W1 ; agg = scatter(norm * h) ; hin = relu(agg + b1)
    k_gemm<D_FEAT><<<N_NODES / 32, NT>>>(x, W1, p_h);
    k_self_init<<<featBlocks, NT>>>(p_h);
    k_scatter<<<scatterBlocks, NT>>>(src, dst, p_h);
    k_bias_relu<<<featBlocks, NT>>>(b1);

    // layer 2: h = hin@W2 ; agg = scatter(norm * h)   (bias+relu fused in pool)
    k_gemm<HIDDEN><<<N_NODES / 32, NT>>>(p_hin, W2, p_h);
    k_self_init<<<featBlocks, NT>>>(p_h);
    k_scatter<<<scatterBlocks, NT>>>(src, dst, p_h);

    // pooling + head
    k_pool_zero<<<(N_GRAPHS * HIDDEN + NT - 1) / NT, NT>>>();
    k_pool<<<1024, HIDDEN>>>(batch, b2);
    k_head<<<1, N_GRAPHS>>>(linW, linb, out);
}

// round 5
// speedup vs baseline: 1.0168x; 1.0168x over previous
#include <cuda_runtime.h>
#include <cuda_bf16.h>
#include <math.h>

#define N_NODES  100000
#define N_EDGES  3200000
#define D_FEAT   128
#define HIDDEN   64
#define N_GRAPHS 64
#define N_CLASSES 10

// ---------------- scratch (device globals; no allocation allowed) -----------
__device__ __align__(16) float g_deg[N_NODES];
__device__ __align__(16) float g_dinv[N_NODES];
__device__ __align__(16) float g_h[N_NODES * HIDDEN];     // transformed features (X@W)
__device__ __align__(16) float g_hin[N_NODES * HIDDEN];   // relu'd layer output
__device__ __align__(16) float g_agg[N_NODES * HIDDEN];   // scatter accumulator
__device__ __align__(16) float g_gsum[N_GRAPHS * HIDDEN];
__device__ __align__(16) float g_gcnt[N_GRAPHS];

// ---------------- degree / norm ---------------------------------------------
__global__ void k_init_deg() {
    int i = blockIdx.x * blockDim.x + threadIdx.x;
    if (i < N_NODES) g_deg[i] = 1.0f;   // self-loop
}

__global__ void k_deg_edges(const int* __restrict__ dst) {
    int e = blockIdx.x * blockDim.x + threadIdx.x;
    if (e < N_EDGES) atomicAdd(&g_deg[dst[e]], 1.0f);
}

__global__ void k_dinv() {
    int i = blockIdx.x * blockDim.x + threadIdx.x;
    if (i < N_NODES) g_dinv[i] = rsqrtf(g_deg[i]);   // deg >= 1 always
}

// ---------------- dense GEMM: Y[N,64] = X[N,K] @ W[K,64] --------------------
// Block computes 32 rows x 64 cols. Thread tile: 4 rows x 2 cols (c, c+32).
template <int K>
__global__ void k_gemm(const float* __restrict__ X, const float* __restrict__ W,
                       float* __restrict__ Y) {
    __shared__ float Ws[K * 64];
    __shared__ float Xs[32 * K];
    const int t = threadIdx.x;
    const int row0 = blockIdx.x * 32;

    for (int i = t; i < K * 64; i += 256) Ws[i] = W[i];
    for (int i = t; i < 32 * K; i += 256) Xs[i] = X[(size_t)row0 * K + i];
    __syncthreads();

    const int c0 = t & 31;          // cols c0 and c0+32 (conflict-free Ws reads)
    const int r0 = (t >> 5) * 4;    // 4 consecutive local rows

    float acc[4][2] = {};
#pragma unroll 4
    for (int k = 0; k < K; k++) {
        float w0 = Ws[k * 64 + c0];
        float w1 = Ws[k * 64 + c0 + 32];
#pragma unroll
        for (int i = 0; i < 4; i++) {
            float xv = Xs[(r0 + i) * K + k];
            acc[i][0] += xv * w0;
            acc[i][1] += xv * w1;
        }
    }
#pragma unroll
    for (int i = 0; i < 4; i++) {
        size_t base = (size_t)(row0 + r0 + i) * 64;
        Y[base + c0]      = acc[i][0];
        Y[base + c0 + 32] = acc[i][1];
    }
}

// ---------------- self-loop init: agg = h * dinv^2 --------------------------
__global__ void k_self_init(const float* __restrict__ h) {
    int i = blockIdx.x * blockDim.x + threadIdx.x;   // over N*H/4 float4 chunks
    if (i >= N_NODES * HIDDEN / 4) return;
    int node = i / (HIDDEN / 4);
    float s = g_dinv[node]; s *= s;
    float4 v = reinterpret_cast<const float4*>(h)[i];
    v.x *= s; v.y *= s; v.z *= s; v.w *= s;
    reinterpret_cast<float4*>(g_agg)[i] = v;
}

// ---------------- edge scatter: agg[dst] += h[src] * dinv[s]*dinv[d] --------
// 16 threads per edge, one float4 gather each; 4 scalar atomicAdd (-> REDG).
__global__ void k_scatter(const int* __restrict__ src,
                          const int* __restrict__ dst,
                          const float* __restrict__ h) {
    long long tid = (long long)blockIdx.x * blockDim.x + threadIdx.x;
    int e = (int)(tid >> 4);
    if (e >= N_EDGES) return;
    int c = (int)(tid & 15);
    int s = src[e];
    int d = dst[e];
    float w = g_dinv[s] * g_dinv[d];
    float4 v = *reinterpret_cast<const float4*>(h + (size_t)s * 64 + c * 4);
    float* p = g_agg + (size_t)d * 64 + c * 4;
    atomicAdd(p + 0, v.x * w);
    atomicAdd(p + 1, v.y * w);
    atomicAdd(p + 2, v.z * w);
    atomicAdd(p + 3, v.w * w);
}

// ---------------- bias + relu: hin = relu(agg + b) ---------------------------
__global__ void k_bias_relu(const float* __restrict__ b) {
    int i = blockIdx.x * blockDim.x + threadIdx.x;   // over N*H/4 float4 chunks
    if (i >= N_NODES * HIDDEN / 4) return;
    int f4 = i & (HIDDEN / 4 - 1);
    float4 bb = reinterpret_cast<const float4*>(b)[f4];
    float4 v = reinterpret_cast<const float4*>(g_agg)[i];
    v.x = fmaxf(v.x + bb.x, 0.f);
    v.y = fmaxf(v.y + bb.y, 0.f);
    v.z = fmaxf(v.z + bb.z, 0.f);
    v.w = fmaxf(v.w + bb.w, 0.f);
    reinterpret_cast<float4*>(g_hin)[i] = v;
}

// ---------------- pooling ----------------------------------------------------
__global__ void k_pool_zero() {
    int i = blockIdx.x * blockDim.x + threadIdx.x;
    if (i < N_GRAPHS * HIDDEN) g_gsum[i] = 0.f;
    if (i < N_GRAPHS) g_gcnt[i] = 0.f;
}

// batch is sorted -> run-length accumulate per block, flush on graph change.
// Applies bias b2 + relu inline (layer-2 epilogue fused here).
__global__ void k_pool(const int* __restrict__ batch,
                       const float* __restrict__ b2) {
    const int f = threadIdx.x;  // 0..63
    const int chunk = (N_NODES + gridDim.x - 1) / gridDim.x;
    int n0 = blockIdx.x * chunk;
    if (n0 >= N_NODES) return;
    int n1 = min(n0 + chunk, N_NODES);

    const float bf = b2[f];
    int cur = batch[n0];
    float acc = 0.f, cnt = 0.f;
    for (int n = n0; n < n1; n++) {
        int bt = batch[n];
        if (bt != cur) {
            atomicAdd(&g_gsum[cur * HIDDEN + f], acc);
            if (f == 0) atomicAdd(&g_gcnt[cur], cnt);
            acc = 0.f; cnt = 0.f; cur = bt;
        }
        acc += fmaxf(g_agg[(size_t)n * HIDDEN + f] + bf, 0.f);
        cnt += 1.f;
    }
    atomicAdd(&g_gsum[cur * HIDDEN + f], acc);
    if (f == 0) atomicAdd(&g_gcnt[cur], cnt);
}

// ---------------- head: mean, linear, log_softmax ----------------------------
__global__ void k_head(const float* __restrict__ linW, const float* __restrict__ linb,
                       float* __restrict__ out) {
    int g = threadIdx.x;
    if (g >= N_GRAPHS) return;
    float inv = 1.0f / fmaxf(g_gcnt[g], 1.0f);
    float logits[N_CLASSES];
#pragma unroll
    for (int c = 0; c < N_CLASSES; c++) logits[c] = linb[c];
    for (int f = 0; f < HIDDEN; f++) {
        float p = g_gsum[g * HIDDEN + f] * inv;
#pragma unroll
        for (int c = 0; c < N_CLASSES; c++) logits[c] += p * linW[f * N_CLASSES + c];
    }
    float m = logits[0];
#pragma unroll
    for (int c = 1; c < N_CLASSES; c++) m = fmaxf(m, logits[c]);
    float s = 0.f;
#pragma unroll
    for (int c = 0; c < N_CLASSES; c++) s += expf(logits[c] - m);
    float l = logf(s) + m;
#pragma unroll
    for (int c = 0; c < N_CLASSES; c++) out[g * N_CLASSES + c] = logits[c] - l;
}

// ---------------- launch ------------------------------------------------------
extern "C" void kernel_launch(void* const* d_in, const int* in_sizes, int n_in,
                              void* d_out, int out_size) {
    const float* x     = (const float*)d_in[0];
    const int*   ei    = (const int*)d_in[1];     // JAX x64 disabled -> int32
    const int*   batch = (const int*)d_in[2];
    const float* W1    = (const float*)d_in[3];
    const float* b1    = (const float*)d_in[4];
    const float* W2    = (const float*)d_in[5];
    const float* b2    = (const float*)d_in[6];
    const float* linW  = (const float*)d_in[7];
    const float* linb  = (const float*)d_in[8];
    float* out = (float*)d_out;

    const int* src = ei;
    const int* dst = ei + N_EDGES;

    float *p_h, *p_hin;
    cudaGetSymbolAddress((void**)&p_h, g_h);
    cudaGetSymbolAddress((void**)&p_hin, g_hin);

    const int NT = 256;
    const int nodeBlocks = (N_NODES + NT - 1) / NT;
    const int edgeBlocks = (N_EDGES + NT - 1) / NT;
    const int featChunks = N_NODES * HIDDEN / 4;
    const int featBlocks = (featChunks + NT - 1) / NT;
    const long long scatterThreads = (long long)N_EDGES * 16;
    const int scatterBlocks = (int)((scatterThreads + NT - 1) / NT);

    // normalization
    k_init_deg<<<nodeBlocks, NT>>>();
    k_deg_edges<<<edgeBlocks, NT>>>(dst);
    k_dinv<<<nodeBlocks, NT>>>();

    // layer 1: h = x@W1 ; agg = scatter(norm * h) ; hin = relu(agg + b1)
    k_gemm<D_FEAT><<<N_NODES / 32, NT>>>(x, W1, p_h);
    k_self_init<<<featBlocks, NT>>>(p_h);
    k_scatter<<<scatterBlocks, NT>>>(src, dst, p_h);
    k_bias_relu<<<featBlocks, NT>>>(b1);

    // layer 2: h = hin@W2 ; agg = scatter(norm * h)   (bias+relu fused in pool)
    k_gemm<HIDDEN><<<N_NODES / 32, NT>>>(p_hin, W2, p_h);
    k_self_init<<<featBlocks, NT>>>(p_h);
    k_scatter<<<scatterBlocks, NT>>>(src, dst, p_h);

    // pooling + head
    k_pool_zero<<<(N_GRAPHS * HIDDEN + NT - 1) / NT, NT>>>();
    k_pool<<<1024, HIDDEN>>>(batch, b2);
    k_head<<<1, N_GRAPHS>>>(linW, linb, out);
}